// round 4
// baseline (speedup 1.0000x reference)
#include <cuda_runtime.h>

namespace {
constexpr int   Bb     = 256;
constexpr int   Nn     = 128;
constexpr int   Mm     = 192;
constexpr int   PA     = 129;   // smem pitch (odd -> conflict-free rows AND columns)
constexpr int   PH     = 129;
constexpr float RHO    = 0.1f;
constexpr float SIGMA  = 1e-6f;
constexpr float ALPHA  = 1.6f;
constexpr int   NITERS = 400;
constexpr int   NT     = 256;

// shared memory layout (in floats); every offset is a multiple of 4 (16B aligned)
constexpr int OFF_A   = 0;
constexpr int OFF_H   = OFF_A + Mm * PA;
constexpr int OFF_Q   = OFF_H + Nn * PH;
constexpr int OFF_L   = OFF_Q + Nn;
constexpr int OFF_U   = OFF_L + Mm;
constexpr int OFF_X   = OFF_U + Mm;
constexpr int OFF_Z   = OFF_X + Nn;
constexpr int OFF_Y   = OFF_Z + Mm;
constexpr int OFF_W   = OFF_Y + Mm;
constexpr int OFF_RHS = OFF_W + Mm;
constexpr int OFF_XT  = OFF_RHS + Nn;
constexpr int OFF_ZT  = OFF_XT + Nn;
constexpr int OFF_RK  = OFF_ZT + Mm;         // row-k snapshot for GJ
constexpr int OFF_CK  = OFF_RK + Nn;         // col-k snapshot for GJ
constexpr int SMEM_FLOATS = OFF_CK + Nn;     // 43200 floats = 172800 B
static_assert((OFF_W   & 3) == 0, "");
static_assert((OFF_RHS & 3) == 0, "");
static_assert((OFF_XT  & 3) == 0, "");
static_assert(SMEM_FLOATS * 4 <= 227 * 1024, "");
}

extern __shared__ float smem[];

__global__ __launch_bounds__(NT, 1)
void osqp_admm_kernel(const float* __restrict__ gP,
                      const float* __restrict__ gq,
                      const float* __restrict__ gA,
                      const float* __restrict__ gl,
                      const float* __restrict__ gu,
                      float* __restrict__ gout)
{
    const int b   = blockIdx.x;
    const int tid = threadIdx.x;

    float* sA   = smem + OFF_A;
    float* sH   = smem + OFF_H;   // H, then H^{-1} in place
    float* sq   = smem + OFF_Q;
    float* sl   = smem + OFF_L;
    float* su   = smem + OFF_U;
    float* sx   = smem + OFF_X;
    float* sz   = smem + OFF_Z;
    float* sy   = smem + OFF_Y;
    float* sw   = smem + OFF_W;   // w = rho*z - y
    float* srhs = smem + OFF_RHS;
    float* sxt  = smem + OFF_XT;
    float* szt  = smem + OFF_ZT;
    float* srk  = smem + OFF_RK;
    float* sck  = smem + OFF_CK;

    // ------------------------------------------------------------------
    // Phase 0: load A (pitched), H = P + sigma*I, vectors; init state = 0
    // ------------------------------------------------------------------
    {
        const float* pA = gA + (size_t)b * Mm * Nn;
        for (int idx = tid; idx < Mm * Nn; idx += NT)
            sA[(idx >> 7) * PA + (idx & 127)] = pA[idx];

        const float* pP = gP + (size_t)b * Nn * Nn;
        for (int idx = tid; idx < Nn * Nn; idx += NT) {
            int i = idx >> 7, j = idx & 127;
            float v = pP[idx];
            if (i == j) v += SIGMA;
            sH[i * PH + j] = v;
        }
        for (int n = tid; n < Nn; n += NT) { sq[n] = gq[(size_t)b * Nn + n]; sx[n] = 0.f; }
        for (int m = tid; m < Mm; m += NT) {
            sl[m] = gl[(size_t)b * Mm + m];
            su[m] = gu[(size_t)b * Mm + m];
            sz[m] = 0.f; sy[m] = 0.f; sw[m] = 0.f;
        }
    }
    __syncthreads();

    // ------------------------------------------------------------------
    // Phase 1: H += rho * A^T A    (8x8 register tile per thread)
    // ------------------------------------------------------------------
    {
        const int ty = tid >> 4;
        const int tx = tid & 15;
        const int i0 = ty * 8;
        float acc[8][8];
        #pragma unroll
        for (int r = 0; r < 8; r++)
            #pragma unroll
            for (int c = 0; c < 8; c++) acc[r][c] = 0.f;

        #pragma unroll 2
        for (int m = 0; m < Mm; m++) {
            const float* row = sA + m * PA;
            float av[8], bv[8];
            #pragma unroll
            for (int r = 0; r < 8; r++) av[r] = row[i0 + r];
            #pragma unroll
            for (int c = 0; c < 8; c++) bv[c] = row[tx + 16 * c];
            #pragma unroll
            for (int r = 0; r < 8; r++)
                #pragma unroll
                for (int c = 0; c < 8; c++)
                    acc[r][c] += av[r] * bv[c];
        }
        #pragma unroll
        for (int r = 0; r < 8; r++)
            #pragma unroll
            for (int c = 0; c < 8; c++)
                sH[(i0 + r) * PH + tx + 16 * c] += RHO * acc[r][c];
    }
    __syncthreads();

    // ------------------------------------------------------------------
    // Phase 2: in-place Gauss-Jordan inverse of H (SPD -> no pivoting)
    // ------------------------------------------------------------------
    for (int k = 0; k < Nn; k++) {
        const float piv = sH[k * PH + k];
        const float p   = 1.0f / piv;
        if (tid < Nn) srk[tid] = sH[k * PH + tid];
        else          sck[tid - Nn] = sH[(tid - Nn) * PH + k];
        __syncthreads();

        const int  j   = tid & 127;
        const int  i0  = (tid >> 7) * 64;
        const float rs = srk[j] * p;
        const bool jk  = (j == k);
        #pragma unroll 4
        for (int i = i0; i < i0 + 64; i++) {
            float hij = sH[i * PH + j];
            float f   = sck[i];
            float nv;
            if (i == k) nv = jk ? p : rs;
            else        nv = jk ? (-f * p) : fmaf(-f, rs, hij);
            sH[i * PH + j] = nv;
        }
        __syncthreads();
    }
    // sH now holds M1 = H^{-1} (symmetric up to rounding)

    // ------------------------------------------------------------------
    // Phase 3: 400 ADMM iterations entirely in SMEM.
    //   rhs = sigma*x - q + A^T w          (w = rho*z - y)
    //   xt  = M1 * rhs                     (M1 symmetric -> column read as rows)
    //   zt  = A * xt
    //   x   = alpha*xt + (1-alpha)*x
    //   zc  = alpha*zt + (1-alpha)*z
    //   z   = clip(zc + y/rho, l, u);  y += rho*(zc - z);  w = rho*z - y
    // ------------------------------------------------------------------
    for (int it = 0; it < NITERS; it++) {
        // ---- rhs = sigma*x - q + A^T w  (threads 0..127, column tid) ----
        if (tid < Nn) {
            float a0 = 0.f, a1 = 0.f;
            #pragma unroll 2
            for (int m0 = 0; m0 < Mm; m0 += 8) {
                float4 w0 = *reinterpret_cast<const float4*>(sw + m0);
                float4 w1 = *reinterpret_cast<const float4*>(sw + m0 + 4);
                const float* ap = sA + m0 * PA + tid;
                a0 = fmaf(ap[0 * PA], w0.x, a0); a1 = fmaf(ap[1 * PA], w0.y, a1);
                a0 = fmaf(ap[2 * PA], w0.z, a0); a1 = fmaf(ap[3 * PA], w0.w, a1);
                a0 = fmaf(ap[4 * PA], w1.x, a0); a1 = fmaf(ap[5 * PA], w1.y, a1);
                a0 = fmaf(ap[6 * PA], w1.z, a0); a1 = fmaf(ap[7 * PA], w1.w, a1);
            }
            srhs[tid] = fmaf(SIGMA, sx[tid], (a0 + a1) - sq[tid]);
        }
        __syncthreads();

        // ---- xt = M1 * rhs  (threads 0..127) ----
        if (tid < Nn) {
            float a0 = 0.f, a1 = 0.f;
            #pragma unroll 2
            for (int j0 = 0; j0 < Nn; j0 += 8) {
                float4 r0 = *reinterpret_cast<const float4*>(srhs + j0);
                float4 r1 = *reinterpret_cast<const float4*>(srhs + j0 + 4);
                const float* hp = sH + j0 * PH + tid;
                a0 = fmaf(hp[0 * PH], r0.x, a0); a1 = fmaf(hp[1 * PH], r0.y, a1);
                a0 = fmaf(hp[2 * PH], r0.z, a0); a1 = fmaf(hp[3 * PH], r0.w, a1);
                a0 = fmaf(hp[4 * PH], r1.x, a0); a1 = fmaf(hp[5 * PH], r1.y, a1);
                a0 = fmaf(hp[6 * PH], r1.z, a0); a1 = fmaf(hp[7 * PH], r1.w, a1);
            }
            sxt[tid] = a0 + a1;
        }
        __syncthreads();

        // ---- zt = A*xt (threads 0..191); x update (threads 192..255) ----
        if (tid < Mm) {
            float a0 = 0.f, a1 = 0.f;
            const float* ap = sA + tid * PA;
            #pragma unroll 2
            for (int n0 = 0; n0 < Nn; n0 += 8) {
                float4 x0 = *reinterpret_cast<const float4*>(sxt + n0);
                float4 x1 = *reinterpret_cast<const float4*>(sxt + n0 + 4);
                a0 = fmaf(ap[n0 + 0], x0.x, a0); a1 = fmaf(ap[n0 + 1], x0.y, a1);
                a0 = fmaf(ap[n0 + 2], x0.z, a0); a1 = fmaf(ap[n0 + 3], x0.w, a1);
                a0 = fmaf(ap[n0 + 4], x1.x, a0); a1 = fmaf(ap[n0 + 5], x1.y, a1);
                a0 = fmaf(ap[n0 + 6], x1.z, a0); a1 = fmaf(ap[n0 + 7], x1.w, a1);
            }
            szt[tid] = a0 + a1;
        } else {
            const int base = (tid - Mm) * 2;   // 64 threads * 2 = 128 elements
            #pragma unroll
            for (int r = 0; r < 2; r++) {
                const int n = base + r;
                sx[n] = ALPHA * sxt[n] + (1.0f - ALPHA) * sx[n];
            }
        }
        __syncthreads();

        // ---- z / y update + next iteration's w (threads 0..191) ----
        if (tid < Mm) {
            const float zc = ALPHA * szt[tid] + (1.0f - ALPHA) * sz[tid];
            const float yv = sy[tid];
            const float v  = zc + yv * (1.0f / RHO);
            const float zn = fminf(fmaxf(v, sl[tid]), su[tid]);
            const float yn = fmaf(RHO, zc - zn, yv);
            sz[tid] = zn;
            sy[tid] = yn;
            sw[tid] = fmaf(RHO, zn, -yn);
        }
        __syncthreads();
    }

    // ------------------------------------------------------------------
    // Output
    // ------------------------------------------------------------------
    for (int n = tid; n < Nn; n += NT)
        gout[(size_t)b * Nn + n] = sx[n];
}

extern "C" void kernel_launch(void* const* d_in, const int* in_sizes, int n_in,
                              void* d_out, int out_size)
{
    const float* P = (const float*)d_in[0];   // (256,128,128)
    const float* q = (const float*)d_in[1];   // (256,128)
    const float* A = (const float*)d_in[2];   // (256,192,128)
    const float* l = (const float*)d_in[3];   // (256,192)
    const float* u = (const float*)d_in[4];   // (256,192)
    float* out = (float*)d_out;               // (256,128)

    const int smem_bytes = SMEM_FLOATS * (int)sizeof(float);
    // Unconditional (no static guard — determinism rule). Not stream-ordered,
    // so legal during graph capture; idempotent across calls.
    cudaFuncSetAttribute(osqp_admm_kernel,
                         cudaFuncAttributeMaxDynamicSharedMemorySize,
                         smem_bytes);
    osqp_admm_kernel<<<Bb, NT, smem_bytes>>>(P, q, A, l, u, out);
}

// round 5
// speedup vs baseline: 1.0548x; 1.0548x over previous
#include <cuda_runtime.h>

namespace {
constexpr int   Bb     = 256;
constexpr int   Nn     = 128;
constexpr int   Mm     = 192;
constexpr int   PA     = 129;   // smem pitch (odd -> conflict-free rows AND columns)
constexpr int   PH     = 129;
constexpr float RHO    = 0.1f;
constexpr float SIGMA  = 1e-6f;
constexpr float ALPHA  = 1.6f;
constexpr int   NITERS = 400;
constexpr int   NT     = 256;

// shared memory layout (floats); all vector offsets multiple of 4 (16B aligned)
constexpr int OFF_A    = 0;                   // 192*129 = 24768
constexpr int OFF_H    = OFF_A + Mm * PA;     // 128*129 = 16512
constexpr int OFF_Q    = OFF_H + Nn * PH;
constexpr int OFF_L    = OFF_Q + Nn;
constexpr int OFF_U    = OFF_L + Mm;
constexpr int OFF_X    = OFF_U + Mm;
constexpr int OFF_Z    = OFF_X + Nn;
constexpr int OFF_Y    = OFF_Z + Mm;
constexpr int OFF_W    = OFF_Y + Mm;
constexpr int OFF_RHS  = OFF_W + Mm;
constexpr int OFF_XT   = OFF_RHS + Nn;
constexpr int OFF_PART = OFF_XT + Nn;         // 256 floats: split-K partials / GJ snapshots
constexpr int SMEM_FLOATS = OFF_PART + 256;   // 43008 floats = 172032 B
static_assert((OFF_W & 3) == 0 && (OFF_RHS & 3) == 0 && (OFF_XT & 3) == 0, "");
static_assert(SMEM_FLOATS * 4 <= 227 * 1024, "");
}

extern __shared__ float smem[];

__global__ __launch_bounds__(NT, 1)
void osqp_admm_kernel(const float* __restrict__ gP,
                      const float* __restrict__ gq,
                      const float* __restrict__ gA,
                      const float* __restrict__ gl,
                      const float* __restrict__ gu,
                      float* __restrict__ gout)
{
    const int b   = blockIdx.x;
    const int tid = threadIdx.x;

    float* sA    = smem + OFF_A;
    float* sH    = smem + OFF_H;    // H, then H^{-1} in place
    float* sq    = smem + OFF_Q;
    float* sl    = smem + OFF_L;
    float* su    = smem + OFF_U;
    float* sx    = smem + OFF_X;
    float* sz    = smem + OFF_Z;
    float* sy    = smem + OFF_Y;
    float* sw    = smem + OFF_W;    // w = rho*z - y
    float* srhs  = smem + OFF_RHS;
    float* sxt   = smem + OFF_XT;
    float* spart = smem + OFF_PART; // split-K partials; GJ row/col snapshots

    // ------------------------------------------------------------------
    // Phase 0: load A (pitched), H = P + sigma*I, vectors; init state = 0
    // ------------------------------------------------------------------
    {
        const float* pA = gA + (size_t)b * Mm * Nn;
        for (int idx = tid; idx < Mm * Nn; idx += NT)
            sA[(idx >> 7) * PA + (idx & 127)] = pA[idx];

        const float* pP = gP + (size_t)b * Nn * Nn;
        for (int idx = tid; idx < Nn * Nn; idx += NT) {
            int i = idx >> 7, j = idx & 127;
            float v = pP[idx];
            if (i == j) v += SIGMA;
            sH[i * PH + j] = v;
        }
        for (int n = tid; n < Nn; n += NT) { sq[n] = gq[(size_t)b * Nn + n]; sx[n] = 0.f; }
        for (int m = tid; m < Mm; m += NT) {
            sl[m] = gl[(size_t)b * Mm + m];
            su[m] = gu[(size_t)b * Mm + m];
            sz[m] = 0.f; sy[m] = 0.f; sw[m] = 0.f;
        }
    }
    __syncthreads();

    // ------------------------------------------------------------------
    // Phase 1: H += rho * A^T A    (8x8 register tile per thread)
    // ------------------------------------------------------------------
    {
        const int ty = tid >> 4;
        const int tx = tid & 15;
        const int i0 = ty * 8;
        float acc[8][8];
        #pragma unroll
        for (int r = 0; r < 8; r++)
            #pragma unroll
            for (int c = 0; c < 8; c++) acc[r][c] = 0.f;

        #pragma unroll 2
        for (int m = 0; m < Mm; m++) {
            const float* row = sA + m * PA;
            float av[8], bv[8];
            #pragma unroll
            for (int r = 0; r < 8; r++) av[r] = row[i0 + r];
            #pragma unroll
            for (int c = 0; c < 8; c++) bv[c] = row[tx + 16 * c];
            #pragma unroll
            for (int r = 0; r < 8; r++)
                #pragma unroll
                for (int c = 0; c < 8; c++)
                    acc[r][c] += av[r] * bv[c];
        }
        #pragma unroll
        for (int r = 0; r < 8; r++)
            #pragma unroll
            for (int c = 0; c < 8; c++)
                sH[(i0 + r) * PH + tx + 16 * c] += RHO * acc[r][c];
    }
    __syncthreads();

    // ------------------------------------------------------------------
    // Phase 2: in-place Gauss-Jordan inverse of H (SPD -> no pivoting)
    // ------------------------------------------------------------------
    {
        float* srk = spart;        // row-k snapshot (128)
        float* sck = spart + Nn;   // col-k snapshot (128)
        for (int k = 0; k < Nn; k++) {
            const float p = 1.0f / sH[k * PH + k];
            if (tid < Nn) srk[tid] = sH[k * PH + tid];
            else          sck[tid - Nn] = sH[(tid - Nn) * PH + k];
            __syncthreads();

            const int  j   = tid & 127;
            const int  i0  = (tid >> 7) * 64;
            const float rs = srk[j] * p;
            const bool jk  = (j == k);
            #pragma unroll 4
            for (int i = i0; i < i0 + 64; i++) {
                float hij = sH[i * PH + j];
                float f   = sck[i];
                float nv;
                if (i == k) nv = jk ? p : rs;
                else        nv = jk ? (-f * p) : fmaf(-f, rs, hij);
                sH[i * PH + j] = nv;
            }
            __syncthreads();
        }
    }
    // sH now holds M1 = H^{-1} (symmetric up to rounding)

    // ------------------------------------------------------------------
    // Phase 3: 400 ADMM iterations, all 256 threads busy via split-K.
    //   rhs = sigma*x - q + A^T w
    //   xt  = M1 * rhs       (M1 symmetric -> column read as rows)
    //   x   = alpha*xt + (1-alpha)*x
    //   zt  = A*xt; zc = alpha*zt+(1-alpha)*z
    //   z   = clip(zc + y/rho, l, u); y += rho*(zc - z); w = rho*z - y
    // ------------------------------------------------------------------
    const int h  = tid >> 7;      // split-K half (0/1)
    const int nc = tid & 127;     // column / row index within half

    for (int it = 0; it < NITERS; it++) {
        // ---- P1: partial A^T w, all 256 threads (96 terms each) ----
        {
            float a0 = 0.f, a1 = 0.f, a2 = 0.f, a3 = 0.f;
            const float* ap = sA + (h * 96) * PA + nc;
            const float* wp = sw + h * 96;
            #pragma unroll 3
            for (int mm = 0; mm < 96; mm += 8) {
                float4 w0 = *reinterpret_cast<const float4*>(wp + mm);
                float4 w1 = *reinterpret_cast<const float4*>(wp + mm + 4);
                const float* a = ap + mm * PA;
                a0 = fmaf(a[0 * PA], w0.x, a0);
                a1 = fmaf(a[1 * PA], w0.y, a1);
                a2 = fmaf(a[2 * PA], w0.z, a2);
                a3 = fmaf(a[3 * PA], w0.w, a3);
                a0 = fmaf(a[4 * PA], w1.x, a0);
                a1 = fmaf(a[5 * PA], w1.y, a1);
                a2 = fmaf(a[6 * PA], w1.z, a2);
                a3 = fmaf(a[7 * PA], w1.w, a3);
            }
            spart[tid] = (a0 + a1) + (a2 + a3);
        }
        __syncthreads();

        // ---- P2: combine rhs (128 threads) ----
        if (tid < Nn)
            srhs[tid] = fmaf(SIGMA, sx[tid],
                             (spart[tid] + spart[tid + 128]) - sq[tid]);
        __syncthreads();

        // ---- P3: partial xt = M1*rhs, all 256 threads (64 terms each) ----
        {
            float a0 = 0.f, a1 = 0.f, a2 = 0.f, a3 = 0.f;
            const float* hp = sH + (h * 64) * PH + nc;
            const float* rp = srhs + h * 64;
            #pragma unroll 2
            for (int jj = 0; jj < 64; jj += 8) {
                float4 r0 = *reinterpret_cast<const float4*>(rp + jj);
                float4 r1 = *reinterpret_cast<const float4*>(rp + jj + 4);
                const float* hh = hp + jj * PH;
                a0 = fmaf(hh[0 * PH], r0.x, a0);
                a1 = fmaf(hh[1 * PH], r0.y, a1);
                a2 = fmaf(hh[2 * PH], r0.z, a2);
                a3 = fmaf(hh[3 * PH], r0.w, a3);
                a0 = fmaf(hh[4 * PH], r1.x, a0);
                a1 = fmaf(hh[5 * PH], r1.y, a1);
                a2 = fmaf(hh[6 * PH], r1.z, a2);
                a3 = fmaf(hh[7 * PH], r1.w, a3);
            }
            spart[tid] = (a0 + a1) + (a2 + a3);
        }
        __syncthreads();

        // ---- P4: combine xt + x update (128 threads) ----
        if (tid < Nn) {
            const float xtv = spart[tid] + spart[tid + 128];
            sxt[tid] = xtv;
            sx[tid]  = fmaf(ALPHA, xtv, (1.0f - ALPHA) * sx[tid]);
        }
        __syncthreads();

        // ---- P5: zt = A*xt fused with z/y/w update (192 threads) ----
        if (tid < Mm) {
            float a0 = 0.f, a1 = 0.f, a2 = 0.f, a3 = 0.f;
            const float* ap = sA + tid * PA;
            #pragma unroll 4
            for (int n0 = 0; n0 < Nn; n0 += 8) {
                float4 x0 = *reinterpret_cast<const float4*>(sxt + n0);
                float4 x1 = *reinterpret_cast<const float4*>(sxt + n0 + 4);
                a0 = fmaf(ap[n0 + 0], x0.x, a0);
                a1 = fmaf(ap[n0 + 1], x0.y, a1);
                a2 = fmaf(ap[n0 + 2], x0.z, a2);
                a3 = fmaf(ap[n0 + 3], x0.w, a3);
                a0 = fmaf(ap[n0 + 4], x1.x, a0);
                a1 = fmaf(ap[n0 + 5], x1.y, a1);
                a2 = fmaf(ap[n0 + 6], x1.z, a2);
                a3 = fmaf(ap[n0 + 7], x1.w, a3);
            }
            const float zt = (a0 + a1) + (a2 + a3);
            const float zc = fmaf(ALPHA, zt, (1.0f - ALPHA) * sz[tid]);
            const float yv = sy[tid];
            const float v  = fmaf(yv, 1.0f / RHO, zc);
            const float zn = fminf(fmaxf(v, sl[tid]), su[tid]);
            const float yn = fmaf(RHO, zc - zn, yv);
            sz[tid] = zn;
            sy[tid] = yn;
            sw[tid] = fmaf(RHO, zn, -yn);
        }
        __syncthreads();
    }

    // ------------------------------------------------------------------
    // Output
    // ------------------------------------------------------------------
    for (int n = tid; n < Nn; n += NT)
        gout[(size_t)b * Nn + n] = sx[n];
}

extern "C" void kernel_launch(void* const* d_in, const int* in_sizes, int n_in,
                              void* d_out, int out_size)
{
    const float* P = (const float*)d_in[0];   // (256,128,128)
    const float* q = (const float*)d_in[1];   // (256,128)
    const float* A = (const float*)d_in[2];   // (256,192,128)
    const float* l = (const float*)d_in[3];   // (256,192)
    const float* u = (const float*)d_in[4];   // (256,192)
    float* out = (float*)d_out;               // (256,128)

    const int smem_bytes = SMEM_FLOATS * (int)sizeof(float);
    // Unconditional (no static guard). Not stream-ordered -> capture-legal; idempotent.
    cudaFuncSetAttribute(osqp_admm_kernel,
                         cudaFuncAttributeMaxDynamicSharedMemorySize,
                         smem_bytes);
    osqp_admm_kernel<<<Bb, NT, smem_bytes>>>(P, q, A, l, u, out);
}